// round 1
// baseline (speedup 1.0000x reference)
#include <cuda_runtime.h>

typedef unsigned long long ull;

#define SEQ   256
#define BSZ   2048
#define FDIM  5
#define HDIM  64
#define KAUX  8
#define NCOL  1280           // 256 (main gates) + 8*128 (aux gates)
#define BT    16             // batch tile per block
#define NTHR  512
#define NBLK  (BSZ / BT)     // 128

// ---------------- repacked weights (device globals; prep kernel fills) ------
__device__ __align__(16) float g_Ucat[HDIM * NCOL];   // [h][col]  recurrent cat
__device__ __align__(16) float g_Wx[FDIM * NCOL];     // [f][col]  input proj cat
__device__ __align__(16) float g_bcat[NCOL];          // bias cat
__device__ __align__(16) float g_W2[128 * 256];       // [h(0..63)=Wih^T, h(64..127)=Whh^T][j]
__device__ __align__(16) float g_b2[256];             // b_ih + b_hh
__device__ __align__(16) float g_WattT[HDIM * HDIM];  // [g][h] = W_att[h][g]
__device__ __align__(16) float g_linW[HDIM];

// ---------------- f32x2 helpers (FFMA2 path, sm_100+) -----------------------
__device__ __forceinline__ void fma2(ull &d, ull a, ull b) {
    asm("fma.rn.f32x2 %0, %1, %2, %0;" : "+l"(d) : "l"(a), "l"(b));
}
__device__ __forceinline__ ull pkdup(float v) {
    ull r; asm("mov.b64 %0, {%1,%1};" : "=l"(r) : "f"(v)); return r;
}
__device__ __forceinline__ void upk(ull v, float &lo, float &hi) {
    asm("mov.b64 {%0,%1}, %2;" : "=f"(lo), "=f"(hi) : "l"(v));
}

// ---------------- fast activations (fp32, ~1e-6 error) ----------------------
__device__ __forceinline__ float fsig(float x) {
    float e = __expf(-x);
    return __fdividef(1.f, 1.f + e);
}
__device__ __forceinline__ float ftanh(float x) {
    return 2.f * fsig(2.f * x) - 1.f;
}

// ---------------- prep: repack weights --------------------------------------
__global__ void prep_kernel(const float *__restrict__ Wm, const float *__restrict__ Um,
                            const float *__restrict__ bm, const float *__restrict__ Wa,
                            const float *__restrict__ Ua, const float *__restrict__ ba,
                            const float *__restrict__ Watt, const float *__restrict__ Wih,
                            const float *__restrict__ Whh, const float *__restrict__ bih,
                            const float *__restrict__ bhh, const float *__restrict__ linW) {
    int i = blockIdx.x * blockDim.x + threadIdx.x;
    if (i < HDIM * NCOL) {
        int h = i / NCOL, col = i % NCOL;
        float v;
        if (col < 256) v = Um[h * 256 + col];
        else { int cc = col - 256; int k = cc >> 7, j = cc & 127; v = Ua[(k * HDIM + h) * 128 + j]; }
        g_Ucat[i] = v;
    }
    if (i < FDIM * NCOL) {
        int f = i / NCOL, col = i % NCOL;
        float v;
        if (col < 256) v = Wm[f * 256 + col];
        else { int cc = col - 256; int k = cc >> 7, j = cc & 127; v = Wa[(k * FDIM + f) * 128 + j]; }
        g_Wx[i] = v;
    }
    if (i < NCOL) g_bcat[i] = (i < 256) ? bm[i] : ba[i - 256];
    if (i < 128 * 256) {
        int h = i / 256, j = i % 256;
        g_W2[i] = (h < 64) ? Wih[j * 64 + h] : Whh[j * 64 + (h - 64)];
    }
    if (i < 256) g_b2[i] = bih[i] + bhh[i];
    if (i < HDIM * HDIM) { int g = i / HDIM, h = i % HDIM; g_WattT[i] = Watt[h * HDIM + g]; }
    if (i < HDIM) g_linW[i] = linW[i];
}

// ---------------- fused MI-LSTM + LSTM + head kernel ------------------------
// smem layout (floats):
//   Gsm [16][1280]  = 20480   gate pre-activations (phase 1)
//   g2  [16][256]   =  4096   gate pre-activations (phase 2)
//   hh  [16][128]   =  2048   [r][0..63]=h1(cur), [r][64..127]=h2(prev)
//   csm [16][64]    =  1024   c1 (for attention matvec)
//   xsm [9][5][16]  =   720   input values for this timestep
#define SM_G   0
#define SM_G2  20480
#define SM_HH  24576
#define SM_C   26624
#define SM_X   27648
#define SM_TOT 28368

__global__ void __launch_bounds__(NTHR, 1)
mi_kernel(const float *__restrict__ Y,
          const float *__restrict__ X1, const float *__restrict__ X2,
          const float *__restrict__ X3, const float *__restrict__ X4,
          const float *__restrict__ X5, const float *__restrict__ X6,
          const float *__restrict__ X7, const float *__restrict__ X8,
          const float *__restrict__ batt_p, const float *__restrict__ linb_p,
          float *__restrict__ out) {
    extern __shared__ float sm[];
    float *Gsm = sm + SM_G;
    float *g2  = sm + SM_G2;
    float *hh  = sm + SM_HH;
    float *csm = sm + SM_C;
    float *xsm = sm + SM_X;

    const int tid  = threadIdx.x;
    const int warp = tid >> 5, lane = tid & 31;
    const int rg = tid >> 7;          // 0..3  -> rows 4rg..4rg+3
    const int cg = tid & 127;         // 0..127 -> col pair (2cg, 2cg+1) per segment
    const int b0 = blockIdx.x * BT;

    const float batt = *batt_p;
    const float linb = *linb_p;
    const float *xp[9] = {Y, X1, X2, X3, X4, X5, X6, X7, X8};

    // zero initial state
    for (int i = tid; i < 2048; i += NTHR) hh[i] = 0.f;
    for (int i = tid; i < 1024; i += NTHR) csm[i] = 0.f;
    float c1a = 0.f, c1b = 0.f;   // phase-1 cell, h = lane / lane+32 of row `warp`
    float c2a = 0.f, c2b = 0.f;   // phase-2 cell

    // this thread's 5 column segments
    int cols[5], srcs[5];
#pragma unroll
    for (int i = 0; i < 5; i++) {
        int col = 2 * cg + 256 * i;
        cols[i] = col;
        srcs[i] = (col < 256) ? 0 : 1 + ((col - 256) >> 7);
    }

    for (int t = 0; t < SEQ; t++) {
        // ---- stage inputs for this timestep (80 contiguous floats per tensor)
        {
            size_t base = (size_t)t * BSZ * FDIM + (size_t)b0 * FDIM;
            for (int j = tid; j < 9 * 80; j += NTHR) {
                int s = j / 80, rem = j - s * 80;
                int row = rem / 5, f = rem - row * 5;
                xsm[s * 80 + f * 16 + row] = xp[s][base + rem];
            }
        }
        __syncthreads();

        // ---- phase-1 GEMM: G[16][1280] = bias + x@Wx + h1_prev@Ucat
        {
            ull acc[4][5];
#pragma unroll
            for (int i = 0; i < 5; i++) {
                ull bp = *(const ull *)&g_bcat[cols[i]];
                acc[0][i] = bp; acc[1][i] = bp; acc[2][i] = bp; acc[3][i] = bp;
            }
#pragma unroll
            for (int f = 0; f < 5; f++) {
#pragma unroll
                for (int i = 0; i < 5; i++) {
                    ull w = *(const ull *)&g_Wx[f * NCOL + cols[i]];
                    int s = srcs[i];
#pragma unroll
                    for (int r = 0; r < 4; r++) {
                        float xv = xsm[s * 80 + f * 16 + 4 * rg + r];
                        fma2(acc[r][i], pkdup(xv), w);
                    }
                }
            }
#pragma unroll 8
            for (int h = 0; h < HDIM; h++) {
                ull hd[4];
#pragma unroll
                for (int r = 0; r < 4; r++) hd[r] = pkdup(hh[(4 * rg + r) * 128 + h]);
#pragma unroll
                for (int i = 0; i < 5; i++) {
                    ull w = *(const ull *)&g_Ucat[h * NCOL + cols[i]];
#pragma unroll
                    for (int r = 0; r < 4; r++) fma2(acc[r][i], hd[r], w);
                }
            }
#pragma unroll
            for (int r = 0; r < 4; r++)
#pragma unroll
                for (int i = 0; i < 5; i++)
                    *(ull *)&Gsm[(4 * rg + r) * NCOL + cols[i]] = acc[r][i];
        }
        __syncthreads();

        // ---- phase-1 elementwise + attention (warp r owns batch row r)
        {
            const int r = warp;
            const float *Gr = &Gsm[r * NCOL];
            const int h0 = lane, h1 = lane + 32;

            float i0 = fsig(Gr[h0]),        i1 = fsig(Gr[h1]);
            float f0 = fsig(Gr[64 + h0]),   f1 = fsig(Gr[64 + h1]);
            float o0 = fsig(Gr[128 + h0]),  o1 = fsig(Gr[128 + h1]);
            float m0 = ftanh(Gr[192 + h0]), m1 = ftanh(Gr[192 + h1]);

            float l0[9], l1[9];
            l0[0] = i0 * m0; l1[0] = i1 * m1;
#pragma unroll
            for (int k = 0; k < KAUX; k++) {
                const float *Ga = Gr + 256 + 128 * k;
                l0[k + 1] = fsig(Ga[h0]) * ftanh(Ga[64 + h0]);
                l1[k + 1] = fsig(Ga[h1]) * ftanh(Ga[64 + h1]);
            }

            // v = W_att @ c_prev (row-local matvec)
            float v0 = 0.f, v1 = 0.f;
#pragma unroll 8
            for (int g = 0; g < HDIM; g++) {
                float cgv = csm[r * HDIM + g];
                v0 = fmaf(g_WattT[g * HDIM + h0], cgv, v0);
                v1 = fmaf(g_WattT[g * HDIM + h1], cgv, v1);
            }

            // u_k = tanh(l_k . v + b_att); softmax (u in (-1,1): no max needed)
            float e[9], esum = 0.f;
#pragma unroll
            for (int k = 0; k < 9; k++) {
                float d = l0[k] * v0 + l1[k] * v1;
                d += __shfl_xor_sync(0xffffffffu, d, 16);
                d += __shfl_xor_sync(0xffffffffu, d, 8);
                d += __shfl_xor_sync(0xffffffffu, d, 4);
                d += __shfl_xor_sync(0xffffffffu, d, 2);
                d += __shfl_xor_sync(0xffffffffu, d, 1);
                e[k] = __expf(ftanh(d + batt));
                esum += e[k];
            }
            float inv = __fdividef(1.f, esum);
            float L0 = 0.f, L1 = 0.f;
#pragma unroll
            for (int k = 0; k < 9; k++) {
                float a = e[k] * inv;
                L0 = fmaf(a, l0[k], L0);
                L1 = fmaf(a, l1[k], L1);
            }
            float cn0 = fmaf(f0, c1a, L0), cn1 = fmaf(f1, c1b, L1);
            float hn0 = o0 * ftanh(cn0),   hn1 = o1 * ftanh(cn1);
            c1a = cn0; c1b = cn1;
            __syncwarp();                      // matvec reads of csm done
            csm[r * HDIM + h0] = cn0; csm[r * HDIM + h1] = cn1;
            hh[r * 128 + h0] = hn0;   hh[r * 128 + h1] = hn1;
        }
        __syncthreads();

        // ---- phase-2 GEMM: g2[16][256] = b2 + [h1_cur; h2_prev] @ [Wih^T; Whh^T]
        {
            ull acc2[4];
            ull bp = *(const ull *)&g_b2[2 * cg];
            acc2[0] = bp; acc2[1] = bp; acc2[2] = bp; acc2[3] = bp;
#pragma unroll 8
            for (int h = 0; h < 128; h++) {
                ull w = *(const ull *)&g_W2[h * 256 + 2 * cg];
#pragma unroll
                for (int r = 0; r < 4; r++)
                    fma2(acc2[r], pkdup(hh[(4 * rg + r) * 128 + h]), w);
            }
#pragma unroll
            for (int r = 0; r < 4; r++)
                *(ull *)&g2[(4 * rg + r) * 256 + 2 * cg] = acc2[r];
        }
        __syncthreads();

        // ---- phase-2 elementwise + output head (warp r owns row r)
        {
            const int r = warp;
            const float *gr = &g2[r * 256];
            const int j0 = lane, j1 = lane + 32;
            float i0 = fsig(gr[j0]),        i1 = fsig(gr[j1]);
            float f0 = fsig(gr[64 + j0]),   f1 = fsig(gr[64 + j1]);
            float gg0 = ftanh(gr[128 + j0]), gg1 = ftanh(gr[128 + j1]);
            float o0 = fsig(gr[192 + j0]),  o1 = fsig(gr[192 + j1]);
            c2a = fmaf(f0, c2a, i0 * gg0);
            c2b = fmaf(f1, c2b, i1 * gg1);
            float h20 = o0 * ftanh(c2a), h21 = o1 * ftanh(c2b);
            hh[r * 128 + 64 + j0] = h20;
            hh[r * 128 + 64 + j1] = h21;
            float ov = fmaxf(h20, 0.f) * g_linW[j0] + fmaxf(h21, 0.f) * g_linW[j1];
            ov += __shfl_xor_sync(0xffffffffu, ov, 16);
            ov += __shfl_xor_sync(0xffffffffu, ov, 8);
            ov += __shfl_xor_sync(0xffffffffu, ov, 4);
            ov += __shfl_xor_sync(0xffffffffu, ov, 2);
            ov += __shfl_xor_sync(0xffffffffu, ov, 1);
            if (lane == 0) out[(size_t)t * BSZ + b0 + r] = ov + linb;
        }
        __syncthreads();
    }
}

// ---------------- launch ----------------------------------------------------
extern "C" void kernel_launch(void *const *d_in, const int *in_sizes, int n_in,
                              void *d_out, int out_size) {
    (void)in_sizes; (void)n_in; (void)out_size;
    const float *Y    = (const float *)d_in[0];
    const float *x1   = (const float *)d_in[1];
    const float *x2   = (const float *)d_in[2];
    const float *x3   = (const float *)d_in[3];
    const float *x4   = (const float *)d_in[4];
    const float *x5   = (const float *)d_in[5];
    const float *x6   = (const float *)d_in[6];
    const float *x7   = (const float *)d_in[7];
    const float *x8   = (const float *)d_in[8];
    const float *Wm   = (const float *)d_in[9];
    const float *Um   = (const float *)d_in[10];
    const float *bm   = (const float *)d_in[11];
    const float *Wa   = (const float *)d_in[12];
    const float *Ua   = (const float *)d_in[13];
    const float *ba   = (const float *)d_in[14];
    const float *Watt = (const float *)d_in[15];
    const float *batt = (const float *)d_in[16];
    const float *Wih  = (const float *)d_in[17];
    const float *Whh  = (const float *)d_in[18];
    const float *bih  = (const float *)d_in[19];
    const float *bhh  = (const float *)d_in[20];
    const float *linW = (const float *)d_in[21];
    const float *linb = (const float *)d_in[22];
    float *out = (float *)d_out;

    prep_kernel<<<(HDIM * NCOL + 255) / 256, 256>>>(Wm, Um, bm, Wa, Ua, ba, Watt,
                                                    Wih, Whh, bih, bhh, linW);

    static_assert(SM_TOT * 4 < 227 * 1024, "smem");
    cudaFuncSetAttribute(mi_kernel, cudaFuncAttributeMaxDynamicSharedMemorySize,
                         SM_TOT * (int)sizeof(float));
    mi_kernel<<<NBLK, NTHR, SM_TOT * sizeof(float)>>>(Y, x1, x2, x3, x4, x5, x6, x7, x8,
                                                      batt, linb, out);
}